// round 2
// baseline (speedup 1.0000x reference)
#include <cuda_runtime.h>

// EGNN forward, N=50000 nodes, E=1.6M edges, H=32, DX=16, L=2.
// R2: float4 (LDS.128) weight loads from transposed smem tiles + occupancy cap.

#define H   32
#define DX  16
#define NMAX 50048

__device__ __align__(16) float g_x[NMAX * DX];
__device__ __align__(16) float g_h[NMAX * H];
__device__ __align__(16) float g_A[NMAX * H];
__device__ __align__(16) float g_B[NMAX * H];
__device__ __align__(16) float g_magg[NMAX * H];
__device__ __align__(16) float g_tagg[NMAX * DX];
__device__ float g_cnt[NMAX];

__device__ __forceinline__ float silu_f(float v) {
    return v * (1.0f / (1.0f + __expf(-v)));
}

__device__ __forceinline__ void red_add_v4(float* addr, float a, float b, float c, float d) {
    asm volatile("red.global.add.v4.f32 [%0], {%1,%2,%3,%4};"
                 :: "l"(addr), "f"(a), "f"(b), "f"(c), "f"(d)
                 : "memory");
}

// ---------------------------------------------------------------------------
// init
// ---------------------------------------------------------------------------
__global__ __launch_bounds__(128, 4) void init_kernel(
    const float* __restrict__ attrs,
    const float* __restrict__ pos,
    const float* __restrict__ projW,
    const float* __restrict__ embW,
    const float* __restrict__ embB,
    const float* __restrict__ eW1,    // layer0 edge_W1 [32][68]
    const float* __restrict__ eb1,
    int n)
{
    __shared__ __align__(16) float sWa[H][H];   // [k][j] transposed
    __shared__ __align__(16) float sWb[H][H];
    for (int idx = threadIdx.x; idx < H * H; idx += 128) {
        int j = idx >> 5, k = idx & 31;
        sWa[k][j] = eW1[j * 68 + k];
        sWb[k][j] = eW1[j * 68 + 32 + k];
    }
    __syncthreads();

    int i = blockIdx.x * 128 + threadIdx.x;
    if (i >= n) return;

    float p0 = pos[i * 3 + 0], p1 = pos[i * 3 + 1], p2 = pos[i * 3 + 2];
    float xv[DX];
#pragma unroll
    for (int j = 0; j < DX; j++)
        xv[j] = projW[j * 3 + 0] * p0 + projW[j * 3 + 1] * p1 + projW[j * 3 + 2] * p2;

    float4* xo = (float4*)&g_x[i * DX];
#pragma unroll
    for (int q = 0; q < 4; q++)
        xo[q] = make_float4(xv[4 * q], xv[4 * q + 1], xv[4 * q + 2], xv[4 * q + 3]);

    float a0 = attrs[i * 3 + 0], a1 = attrs[i * 3 + 1], a2 = attrs[i * 3 + 2];
    float hv[H];
#pragma unroll
    for (int j = 0; j < H; j++)
        hv[j] = embW[j * 3 + 0] * a0 + embW[j * 3 + 1] * a1 + embW[j * 3 + 2] * a2 + embB[j];

    float4* ho = (float4*)&g_h[i * H];
#pragma unroll
    for (int q = 0; q < 8; q++)
        ho[q] = make_float4(hv[4 * q], hv[4 * q + 1], hv[4 * q + 2], hv[4 * q + 3]);

    float Av[H], Bv[H];
#pragma unroll
    for (int j = 0; j < H; j++) { Av[j] = eb1[j]; Bv[j] = 0.0f; }
#pragma unroll
    for (int k = 0; k < H; k++) {
        float hk = hv[k];
        const float4* wa = (const float4*)&sWa[k][0];
        const float4* wb = (const float4*)&sWb[k][0];
#pragma unroll
        for (int q = 0; q < 8; q++) {
            float4 a = wa[q], b = wb[q];
            Av[4 * q + 0] += a.x * hk; Av[4 * q + 1] += a.y * hk;
            Av[4 * q + 2] += a.z * hk; Av[4 * q + 3] += a.w * hk;
            Bv[4 * q + 0] += b.x * hk; Bv[4 * q + 1] += b.y * hk;
            Bv[4 * q + 2] += b.z * hk; Bv[4 * q + 3] += b.w * hk;
        }
    }
    float4* Ao = (float4*)&g_A[i * H];
    float4* Bo = (float4*)&g_B[i * H];
#pragma unroll
    for (int q = 0; q < 8; q++) {
        Ao[q] = make_float4(Av[4 * q], Av[4 * q + 1], Av[4 * q + 2], Av[4 * q + 3]);
        Bo[q] = make_float4(Bv[4 * q], Bv[4 * q + 1], Bv[4 * q + 2], Bv[4 * q + 3]);
    }

    const float4 z4 = make_float4(0.f, 0.f, 0.f, 0.f);
    float4* mz = (float4*)&g_magg[i * H];
    float4* tz = (float4*)&g_tagg[i * DX];
#pragma unroll
    for (int q = 0; q < 8; q++) mz[q] = z4;
#pragma unroll
    for (int q = 0; q < 4; q++) tz[q] = z4;
    g_cnt[i] = 0.0f;
}

// ---------------------------------------------------------------------------
__global__ void count_kernel(const int* __restrict__ ei, int E)
{
    int e = blockIdx.x * blockDim.x + threadIdx.x;
    if (e < E) atomicAdd(&g_cnt[ei[e]], 1.0f);
}

// ---------------------------------------------------------------------------
// edge kernel
// ---------------------------------------------------------------------------
#define ETPB 128

__global__ __launch_bounds__(ETPB, 4) void edge_kernel(
    const int* __restrict__ ei, int E,
    const float* __restrict__ pos,
    const float* __restrict__ W1,   // [32][68], cols 64..67 used
    const float* __restrict__ W2,   // [32][32]
    const float* __restrict__ b2,
    const float* __restrict__ cW1,  // [32][32]
    const float* __restrict__ cb1,
    const float* __restrict__ cW2)  // [32]
{
    __shared__ __align__(16) float s_W2t[H][H];   // [k][j]
    __shared__ __align__(16) float s_cW1t[H][H];  // [k][j]
    __shared__ float s_wr[H];
    __shared__ float s_we[3][H];
    __shared__ float s_b2[H];
    __shared__ float s_cb1[H];
    __shared__ float s_cw2[H];

    for (int idx = threadIdx.x; idx < H * H; idx += ETPB) {
        int j = idx >> 5, k = idx & 31;
        s_W2t[k][j]  = W2[idx];
        s_cW1t[k][j] = cW1[idx];
    }
    if (threadIdx.x < H) {
        int j = threadIdx.x;
        s_wr[j]    = W1[j * 68 + 64];
        s_we[0][j] = W1[j * 68 + 65];
        s_we[1][j] = W1[j * 68 + 66];
        s_we[2][j] = W1[j * 68 + 67];
        s_b2[j]  = b2[j];
        s_cb1[j] = cb1[j];
        s_cw2[j] = cW2[j];
    }
    __syncthreads();

    int e = blockIdx.x * ETPB + threadIdx.x;
    if (e >= E) return;

    int row = ei[e];
    int col = ei[E + e];

    float ea0 = pos[row * 3 + 0] - pos[col * 3 + 0];
    float ea1 = pos[row * 3 + 1] - pos[col * 3 + 1];
    float ea2 = pos[row * 3 + 2] - pos[col * 3 + 2];

    float cd[DX];
    const float4* xr = (const float4*)&g_x[row * DX];
    const float4* xc = (const float4*)&g_x[col * DX];
    float radial = 0.0f;
#pragma unroll
    for (int q = 0; q < 4; q++) {
        float4 a = xr[q], b = xc[q];
        float d0 = a.x - b.x, d1 = a.y - b.y, d2 = a.z - b.z, d3 = a.w - b.w;
        cd[4 * q + 0] = d0; cd[4 * q + 1] = d1; cd[4 * q + 2] = d2; cd[4 * q + 3] = d3;
        radial += d0 * d0 + d1 * d1 + d2 * d2 + d3 * d3;
    }

    // layer-1 (A/B factored) -> m1 in acc
    float acc[H];
    {
        const float4* Ar = (const float4*)&g_A[row * H];
        const float4* Bc = (const float4*)&g_B[col * H];
#pragma unroll
        for (int q = 0; q < 8; q++) {
            float4 a = Ar[q], b = Bc[q];
            acc[4 * q + 0] = a.x + b.x; acc[4 * q + 1] = a.y + b.y;
            acc[4 * q + 2] = a.z + b.z; acc[4 * q + 3] = a.w + b.w;
        }
#pragma unroll
        for (int j = 0; j < H; j++) {
            acc[j] += s_wr[j] * radial + s_we[0][j] * ea0 + s_we[1][j] * ea1 + s_we[2][j] * ea2;
            acc[j] = silu_f(acc[j]);
        }
    }

    // layer-2: m = silu(W2 m1 + b2), float4 weight loads
    float m[H];
    {
#pragma unroll
        for (int j = 0; j < H; j++) m[j] = s_b2[j];
#pragma unroll
        for (int k = 0; k < H; k++) {
            float mk = acc[k];
            const float4* wr4 = (const float4*)&s_W2t[k][0];
#pragma unroll
            for (int q = 0; q < 8; q++) {
                float4 w = wr4[q];
                m[4 * q + 0] += w.x * mk; m[4 * q + 1] += w.y * mk;
                m[4 * q + 2] += w.z * mk; m[4 * q + 3] += w.w * mk;
            }
        }
#pragma unroll
        for (int j = 0; j < H; j++) m[j] = silu_f(m[j]);
    }

    // coord head
    float cm;
    {
        float cacc[H];
#pragma unroll
        for (int j = 0; j < H; j++) cacc[j] = s_cb1[j];
#pragma unroll
        for (int k = 0; k < H; k++) {
            float mk = m[k];
            const float4* wr4 = (const float4*)&s_cW1t[k][0];
#pragma unroll
            for (int q = 0; q < 8; q++) {
                float4 w = wr4[q];
                cacc[4 * q + 0] += w.x * mk; cacc[4 * q + 1] += w.y * mk;
                cacc[4 * q + 2] += w.z * mk; cacc[4 * q + 3] += w.w * mk;
            }
        }
        cm = 0.0f;
#pragma unroll
        for (int j = 0; j < H; j++) cm += s_cw2[j] * silu_f(cacc[j]);
    }

    float* mago = &g_magg[row * H];
#pragma unroll
    for (int q = 0; q < 8; q++)
        red_add_v4(mago + 4 * q, m[4 * q], m[4 * q + 1], m[4 * q + 2], m[4 * q + 3]);

    float* tago = &g_tagg[row * DX];
#pragma unroll
    for (int q = 0; q < 4; q++)
        red_add_v4(tago + 4 * q,
                   cd[4 * q] * cm, cd[4 * q + 1] * cm, cd[4 * q + 2] * cm, cd[4 * q + 3] * cm);
}

// ---------------------------------------------------------------------------
// node kernel
// ---------------------------------------------------------------------------
#define NTPB 128

__global__ __launch_bounds__(NTPB, 4) void node_kernel(
    const float* __restrict__ nW1,   // [32][64]
    const float* __restrict__ nb1,
    const float* __restrict__ nW2,   // [32][32]
    const float* __restrict__ nb2,
    const float* __restrict__ eW1n,  // next-layer edge_W1 [32][68] or null
    const float* __restrict__ eb1n,
    const float* __restrict__ linW,  // [3][16] or null
    float* __restrict__ out,
    int n)
{
    __shared__ __align__(16) float sN1t[2 * H][H];  // [k][j]
    __shared__ __align__(16) float sN2t[H][H];      // [k][j]
    __shared__ __align__(16) float sEAt[H][H];      // [k][j]
    __shared__ __align__(16) float sEBt[H][H];

    for (int idx = threadIdx.x; idx < H * 2 * H; idx += NTPB) {
        int j = idx >> 6, k = idx & 63;
        sN1t[k][j] = nW1[idx];
    }
    for (int idx = threadIdx.x; idx < H * H; idx += NTPB) {
        int j = idx >> 5, k = idx & 31;
        sN2t[k][j] = nW2[idx];
        if (eW1n) {
            sEAt[k][j] = eW1n[j * 68 + k];
            sEBt[k][j] = eW1n[j * 68 + 32 + k];
        }
    }
    __syncthreads();

    int i = blockIdx.x * NTPB + threadIdx.x;
    if (i >= n) return;

    float cnt = g_cnt[i];
    float inv = 1.0f / fmaxf(cnt, 1.0f);

    const float4 z4 = make_float4(0.f, 0.f, 0.f, 0.f);

    float xv[DX];
    float4* xp = (float4*)&g_x[i * DX];
    float4* tp = (float4*)&g_tagg[i * DX];
#pragma unroll
    for (int q = 0; q < 4; q++) {
        float4 a = xp[q], t = tp[q];
        xv[4 * q + 0] = a.x + t.x * inv;
        xv[4 * q + 1] = a.y + t.y * inv;
        xv[4 * q + 2] = a.z + t.z * inv;
        xv[4 * q + 3] = a.w + t.w * inv;
        xp[q] = make_float4(xv[4 * q], xv[4 * q + 1], xv[4 * q + 2], xv[4 * q + 3]);
        tp[q] = z4;
    }

    float hv[H], mg[H];
    float4* hp = (float4*)&g_h[i * H];
    float4* mp = (float4*)&g_magg[i * H];
#pragma unroll
    for (int q = 0; q < 8; q++) {
        float4 a = hp[q];
        hv[4 * q + 0] = a.x; hv[4 * q + 1] = a.y; hv[4 * q + 2] = a.z; hv[4 * q + 3] = a.w;
        float4 b = mp[q];
        mg[4 * q + 0] = b.x; mg[4 * q + 1] = b.y; mg[4 * q + 2] = b.z; mg[4 * q + 3] = b.w;
        mp[q] = z4;
    }

    float u[H];
#pragma unroll
    for (int j = 0; j < H; j++) u[j] = nb1[j];
#pragma unroll
    for (int k = 0; k < H; k++) {
        float v = hv[k];
        const float4* w4 = (const float4*)&sN1t[k][0];
#pragma unroll
        for (int q = 0; q < 8; q++) {
            float4 w = w4[q];
            u[4 * q + 0] += w.x * v; u[4 * q + 1] += w.y * v;
            u[4 * q + 2] += w.z * v; u[4 * q + 3] += w.w * v;
        }
    }
#pragma unroll
    for (int k = 0; k < H; k++) {
        float v = mg[k];
        const float4* w4 = (const float4*)&sN1t[H + k][0];
#pragma unroll
        for (int q = 0; q < 8; q++) {
            float4 w = w4[q];
            u[4 * q + 0] += w.x * v; u[4 * q + 1] += w.y * v;
            u[4 * q + 2] += w.z * v; u[4 * q + 3] += w.w * v;
        }
    }
#pragma unroll
    for (int j = 0; j < H; j++) u[j] = silu_f(u[j]);

    float hn[H];
#pragma unroll
    for (int j = 0; j < H; j++) hn[j] = nb2[j];
#pragma unroll
    for (int k = 0; k < H; k++) {
        float v = u[k];
        const float4* w4 = (const float4*)&sN2t[k][0];
#pragma unroll
        for (int q = 0; q < 8; q++) {
            float4 w = w4[q];
            hn[4 * q + 0] += w.x * v; hn[4 * q + 1] += w.y * v;
            hn[4 * q + 2] += w.z * v; hn[4 * q + 3] += w.w * v;
        }
    }
#pragma unroll
    for (int j = 0; j < H; j++) hn[j] += hv[j];
#pragma unroll
    for (int q = 0; q < 8; q++)
        hp[q] = make_float4(hn[4 * q], hn[4 * q + 1], hn[4 * q + 2], hn[4 * q + 3]);

    if (eW1n) {
        float Av[H], Bv[H];
#pragma unroll
        for (int j = 0; j < H; j++) { Av[j] = eb1n[j]; Bv[j] = 0.0f; }
#pragma unroll
        for (int k = 0; k < H; k++) {
            float v = hn[k];
            const float4* wa = (const float4*)&sEAt[k][0];
            const float4* wb = (const float4*)&sEBt[k][0];
#pragma unroll
            for (int q = 0; q < 8; q++) {
                float4 a = wa[q], b = wb[q];
                Av[4 * q + 0] += a.x * v; Av[4 * q + 1] += a.y * v;
                Av[4 * q + 2] += a.z * v; Av[4 * q + 3] += a.w * v;
                Bv[4 * q + 0] += b.x * v; Bv[4 * q + 1] += b.y * v;
                Bv[4 * q + 2] += b.z * v; Bv[4 * q + 3] += b.w * v;
            }
        }
        float4* Ao = (float4*)&g_A[i * H];
        float4* Bo = (float4*)&g_B[i * H];
#pragma unroll
        for (int q = 0; q < 8; q++) {
            Ao[q] = make_float4(Av[4 * q], Av[4 * q + 1], Av[4 * q + 2], Av[4 * q + 3]);
            Bo[q] = make_float4(Bv[4 * q], Bv[4 * q + 1], Bv[4 * q + 2], Bv[4 * q + 3]);
        }
    }

    if (linW) {
#pragma unroll
        for (int c = 0; c < 3; c++) {
            float acc = 0.0f;
#pragma unroll
            for (int k = 0; k < DX; k++) acc += linW[c * DX + k] * xv[k];
            out[i * 3 + c] = acc;
        }
    }
}

// ---------------------------------------------------------------------------
extern "C" void kernel_launch(void* const* d_in, const int* in_sizes, int n_in,
                              void* d_out, int out_size)
{
    const float* node_attrs = (const float*)d_in[0];
    const float* positions  = (const float*)d_in[1];
    const int*   edge_index = (const int*)  d_in[2];
    const float* proj_W     = (const float*)d_in[3];
    const float* emb_in_W   = (const float*)d_in[4];
    const float* emb_in_b   = (const float*)d_in[5];
    const float* edge_W1    = (const float*)d_in[6];
    const float* edge_b1    = (const float*)d_in[7];
    const float* edge_W2    = (const float*)d_in[8];
    const float* edge_b2    = (const float*)d_in[9];
    const float* node_W1    = (const float*)d_in[10];
    const float* node_b1    = (const float*)d_in[11];
    const float* node_W2    = (const float*)d_in[12];
    const float* node_b2    = (const float*)d_in[13];
    const float* coord_W1   = (const float*)d_in[14];
    const float* coord_b1   = (const float*)d_in[15];
    const float* coord_W2   = (const float*)d_in[16];
    const float* lin_W      = (const float*)d_in[19];

    int n = in_sizes[0] / 3;
    int E = in_sizes[2] / 2;

    float* out = (float*)d_out;

    init_kernel<<<(n + 127) / 128, 128>>>(node_attrs, positions, proj_W,
                                          emb_in_W, emb_in_b,
                                          edge_W1, edge_b1, n);
    count_kernel<<<(E + 255) / 256, 256>>>(edge_index, E);

    for (int l = 0; l < 2; l++) {
        edge_kernel<<<(E + ETPB - 1) / ETPB, ETPB>>>(
            edge_index, E, positions,
            edge_W1 + l * H * 68,
            edge_W2 + l * H * H, edge_b2 + l * H,
            coord_W1 + l * H * H, coord_b1 + l * H,
            coord_W2 + l * H);

        node_kernel<<<(n + NTPB - 1) / NTPB, NTPB>>>(
            node_W1 + l * H * 2 * H, node_b1 + l * H,
            node_W2 + l * H * H,     node_b2 + l * H,
            (l == 0) ? edge_W1 + H * 68 : nullptr,
            (l == 0) ? edge_b1 + H      : nullptr,
            (l == 1) ? lin_W            : nullptr,
            out, n);
    }
}